// round 6
// baseline (speedup 1.0000x reference)
#include <cuda_runtime.h>

#define NBATCH 8192
#define TPB   256   // congruence / reduction kernels
#define TPBJ  128   // Jacobi kernels

// ---------------- device scratch (static, no runtime allocation) ----------------
__device__ float  g_bufA[(size_t)NBATCH * 58 * 58];
__device__ float  g_bufB[(size_t)NBATCH * 58 * 58];
__device__ double g_part[64 * 58 * 58];
__device__ float  g_mean[58 * 58];
__device__ float  g_M0s [58 * 58];
__device__ float  g_M0is[58 * 58];
__device__ float  g_C   [58 * 58];

// ---------------- block reduction helper: returns total in red_[0] ----------------
template<int BS>
__device__ __forceinline__ void block_reduce(float v, float* red_) {
    const int tid  = threadIdx.x;
    const int lane = tid & 31;
    const int wrp  = tid >> 5;
    #pragma unroll
    for (int o = 16; o > 0; o >>= 1) v += __shfl_down_sync(0xffffffffu, v, o);
    if (lane == 0) red_[wrp] = v;
    __syncthreads();
    if (wrp == 0) {
        float t = (lane < BS / 32) ? red_[lane] : 0.0f;
        #pragma unroll
        for (int o = 16; o > 0; o >>= 1) t += __shfl_down_sync(0xffffffffu, t, o);
        if (lane == 0) red_[0] = t;
    }
    __syncthreads();
}

// ---------------- round-robin pairing (circle method, n even) ----------------
__device__ __forceinline__ void pair_of(int r, int k, int n, int& p, int& q) {
    int m = n - 1;
    if (k == 0) { p = n - 1; q = r; }
    else {
        p = r + k; if (p >= m) p -= m;
        q = r - k; if (q < 0)  q += m;
    }
}

// ---------------- block-cooperative cyclic Jacobi on shared A (pitch n+1) ----------------
// On exit: diag(A) = eigenvalues, columns of V = eigenvectors (A0 = V diag V^T).
// Hot loops use a 64-wide power-of-two layout: w -> (k = w>>6, j = w&63).
// Per-round (p,q) pair tables are precomputed into shared memory in both
// row-offset form (p*P) and column-index form (p); the col phase is split into
// two branch-free loops (A then V) between one barrier pair.
template<int n, int BS>
__device__ void jacobi_sym(float* A, float* V) {
    constexpr int P = n + 1;
    constexpr int NPAIR = n / 2;
    const int tid = threadIdx.x;
    __shared__ float cs_[NPAIR], ss_[NPAIR];
    __shared__ int   ppr_[NPAIR], qqr_[NPAIR];   // p*P, q*P (row phase)
    __shared__ int   ppc_[NPAIR], qqc_[NPAIR];   // p,   q   (col phase)
    __shared__ float red_[32];
    __shared__ float s_thr;

    for (int idx = tid; idx < n * n; idx += BS) {
        int i = idx / n, j = idx - i * n;
        V[i * P + j] = (i == j) ? 1.0f : 0.0f;
    }
    float facc = 0.0f;
    for (int idx = tid; idx < n * n; idx += BS) {
        int i = idx / n, j = idx - i * n;
        float v = A[i * P + j];
        facc += v * v;
    }
    __syncthreads();
    block_reduce<BS>(facc, red_);
    // fp32 Jacobi off-diagonal floor: off^2/fro^2 ~ n*eps^2 ~ 8e-13. Stop just above it.
    if (tid == 0) s_thr = red_[0] * 1e-12f + 1e-37f;
    __syncthreads();

    for (int sweep = 0; sweep < 14; ++sweep) {
        for (int r = 0; r < n - 1; ++r) {
            if (tid < NPAIR) {
                int p, q; pair_of(r, tid, n, p, q);
                ppr_[tid] = p * P;  qqr_[tid] = q * P;
                ppc_[tid] = p;      qqc_[tid] = q;
                float app = A[p * P + p], aqq = A[q * P + q], apq = A[p * P + q];
                float c = 1.0f, s = 0.0f;
                if (fabsf(apq) > 1e-38f) {
                    float tau = (aqq - app) / (2.0f * apq);
                    float t = 1.0f / (fabsf(tau) + sqrtf(1.0f + tau * tau));
                    if (tau < 0.0f) t = -t;
                    c = 1.0f / sqrtf(1.0f + t * t);
                    s = t * c;
                }
                cs_[tid] = c; ss_[tid] = s;
            }
            __syncthreads();
            // row phase: A <- J^T A   (k = w>>6, j = w&63)
            for (int w = tid; w < NPAIR * 64; w += BS) {
                int k = w >> 6, j = w & 63;
                if (j < n) {
                    int pP = ppr_[k], qP = qqr_[k];
                    float c = cs_[k], s = ss_[k];
                    float ap = A[pP + j], aq = A[qP + j];
                    A[pP + j] = c * ap - s * aq;
                    A[qP + j] = s * ap + c * aq;
                }
            }
            __syncthreads();
            // col phase: A <- A J (loop 1) ; V <- V J (loop 2) — disjoint arrays,
            // same barrier pair, no per-item pointer select.
            for (int w = tid; w < NPAIR * 64; w += BS) {
                int k = w >> 6, j = w & 63;
                if (j < n) {
                    int jP = j * P;
                    int p = ppc_[k], q = qqc_[k];
                    float c = cs_[k], s = ss_[k];
                    float ap = A[jP + p], aq = A[jP + q];
                    A[jP + p] = c * ap - s * aq;
                    A[jP + q] = s * ap + c * aq;
                }
            }
            for (int w = tid; w < NPAIR * 64; w += BS) {
                int k = w >> 6, j = w & 63;
                if (j < n) {
                    int jP = j * P;
                    int p = ppc_[k], q = qqc_[k];
                    float c = cs_[k], s = ss_[k];
                    float ap = V[jP + p], aq = V[jP + q];
                    V[jP + p] = c * ap - s * aq;
                    V[jP + q] = s * ap + c * aq;
                }
            }
            __syncthreads();
        }
        if (sweep < 3) continue;   // never converges this early for n>=50; skip check cost
        // convergence check (uniform across block)
        float oacc = 0.0f;
        for (int w = tid; w < n * 64; w += BS) {
            int i = w >> 6, j = w & 63;
            if (j < n && i != j) { float v = A[i * P + j]; oacc += v * v; }
        }
        block_reduce<BS>(oacc, red_);
        if (red_[0] < s_thr) break;
        __syncthreads();
    }
    __syncthreads();
}

// ---------------- batched eigen-function: out = U f(Lam) U^T ----------------
#define F_LOG   0
#define F_CLAMP 1

template<int n, int FN>
__global__ void __launch_bounds__(TPBJ) jacobi_fn_kernel(const float* __restrict__ in,
                                                         float* __restrict__ out) {
    constexpr int P = n + 1;
    __shared__ float A[n * P], V[n * P], fv[n];
    const float* g = in  + (size_t)blockIdx.x * n * n;
    float*       o = out + (size_t)blockIdx.x * n * n;
    const int tid = threadIdx.x;
    for (int idx = tid; idx < n * n; idx += TPBJ) {
        int i = idx / n, j = idx - i * n;
        A[i * P + j] = 0.5f * (g[i * n + j] + g[j * n + i]);
    }
    __syncthreads();
    jacobi_sym<n, TPBJ>(A, V);
    if (tid < n) {
        float l = A[tid * P + tid];
        fv[tid] = (FN == F_LOG) ? logf(fmaxf(l, 1e-30f)) : fmaxf(l, 1e-4f);
    }
    __syncthreads();
    // A <- V * diag(fv)
    for (int idx = tid; idx < n * n; idx += TPBJ) {
        int i = idx / n, k = idx - i * n;
        A[i * P + k] = V[i * P + k] * fv[k];
    }
    __syncthreads();
    for (int idx = tid; idx < n * n; idx += TPBJ) {
        int i = idx / n, j = idx - i * n;
        float s = 0.0f;
        #pragma unroll 5
        for (int k = 0; k < n; ++k) s += A[i * P + k] * V[j * P + k];
        o[idx] = s;
    }
}

// ---------------- batched congruence: out = P X P^T  (P: NO x NI) ----------------
template<int NI, int NO>
__global__ void __launch_bounds__(TPB) congr_kernel(const float* __restrict__ Xin,
                                                    const float* __restrict__ Pm,
                                                    float* __restrict__ out) {
    constexpr int PI = NI + 1;
    __shared__ float Xs[NI * PI];
    __shared__ float Ps[NO * PI];
    __shared__ float Ts[NO * PI];
    const float* g = Xin + (size_t)blockIdx.x * NI * NI;
    float*       o = out + (size_t)blockIdx.x * NO * NO;
    const int tid = threadIdx.x;
    for (int idx = tid; idx < NI * NI; idx += TPB) {
        int i = idx / NI, j = idx - i * NI;
        Xs[i * PI + j] = g[idx];
    }
    for (int idx = tid; idx < NO * NI; idx += TPB) {
        int a = idx / NI, i = idx - a * NI;
        Ps[a * PI + i] = Pm[idx];
    }
    __syncthreads();
    for (int idx = tid; idx < NO * NI; idx += TPB) {
        int a = idx / NI, j = idx - a * NI;
        float s = 0.0f;
        #pragma unroll 2
        for (int i = 0; i < NI; ++i) s += Ps[a * PI + i] * Xs[i * PI + j];
        Ts[a * PI + j] = s;
    }
    __syncthreads();
    for (int idx = tid; idx < NO * NO; idx += TPB) {
        int a = idx / NO, b = idx - a * NO;
        float s = 0.0f;
        #pragma unroll 2
        for (int j = 0; j < NI; ++j) s += Ts[a * PI + j] * Ps[b * PI + j];
        o[idx] = s;
    }
}

// ---------------- deterministic two-stage batch-mean reduction ----------------
template<int n>
__global__ void __launch_bounds__(TPB) reduce_partial_kernel(const float* __restrict__ buf,
                                                             double* __restrict__ part) {
    const int b = blockIdx.x;          // 64 blocks
    const int tid = threadIdx.x;
    constexpr int CH = NBATCH / 64;    // 128 matrices per block
    for (int e = tid; e < n * n; e += TPB) {
        double acc = 0.0;
        for (int m = 0; m < CH; ++m)
            acc += (double)buf[((size_t)(b * CH + m)) * (n * n) + e];
        part[(size_t)b * (n * n) + e] = acc;
    }
}

template<int n>
__global__ void __launch_bounds__(TPB) reduce_final_kernel(const double* __restrict__ part,
                                                           float* __restrict__ mean) {
    const int tid = threadIdx.x;
    for (int e = tid; e < n * n; e += TPB) {
        double acc = 0.0;
        for (int b = 0; b < 64; ++b) acc += part[(size_t)b * (n * n) + e];
        mean[e] = (float)(acc * (1.0 / (double)NBATCH));
    }
}

// ---------------- single-matrix stats: M0 -> sqrtm, isqrtm ----------------
template<int n>
__global__ void __launch_bounds__(TPBJ) stats1_kernel(const float* __restrict__ mean,
                                                      float* __restrict__ M0s,
                                                      float* __restrict__ M0is) {
    constexpr int P = n + 1;
    __shared__ float A[n * P], V[n * P], sq[n], isq[n];
    const int tid = threadIdx.x;
    for (int idx = tid; idx < n * n; idx += TPBJ) {
        int i = idx / n, j = idx - i * n;
        A[i * P + j] = 0.5f * (mean[i * n + j] + mean[j * n + i]);
    }
    __syncthreads();
    jacobi_sym<n, TPBJ>(A, V);
    if (tid < n) {
        float l = fmaxf(A[tid * P + tid], 1e-30f);
        float s = sqrtf(l);
        sq[tid] = s;
        isq[tid] = 1.0f / s;
    }
    __syncthreads();
    for (int idx = tid; idx < n * n; idx += TPBJ) {
        int i = idx / n, j = idx - i * n;
        float s1 = 0.0f, s2 = 0.0f;
        for (int k = 0; k < n; ++k) {
            float vv = V[i * P + k] * V[j * P + k];
            s1 += vv * sq[k];
            s2 += vv * isq[k];
        }
        M0s[idx]  = s1;
        M0is[idx] = s2;
    }
}

// ---------------- single-matrix stats2: L, M0s, G_weight -> C = sqrtm(Gw) * isqrtm(G) ----
// G = sym(M0s expm(L) M0s)
template<int n>
__global__ void __launch_bounds__(TPBJ) stats2_kernel(const float* __restrict__ Lmean,
                                                      const float* __restrict__ M0s,
                                                      const float* __restrict__ Gw,
                                                      float* __restrict__ Cout) {
    constexpr int P = n + 1;
    __shared__ float A[n * P], V[n * P], T[n * P], vec[n];
    const int tid = threadIdx.x;
    // E = expm(L)
    for (int idx = tid; idx < n * n; idx += TPBJ) {
        int i = idx / n, j = idx - i * n;
        A[i * P + j] = 0.5f * (Lmean[i * n + j] + Lmean[j * n + i]);
    }
    __syncthreads();
    jacobi_sym<n, TPBJ>(A, V);
    if (tid < n) vec[tid] = expf(A[tid * P + tid]);
    __syncthreads();
    for (int idx = tid; idx < n * n; idx += TPBJ) {     // T = E
        int i = idx / n, j = idx - i * n;
        float s = 0.0f;
        for (int k = 0; k < n; ++k) s += V[i * P + k] * vec[k] * V[j * P + k];
        T[i * P + j] = s;
    }
    __syncthreads();
    for (int idx = tid; idx < n * n; idx += TPBJ) {     // A = M0s * E
        int i = idx / n, j = idx - i * n;
        float s = 0.0f;
        for (int k = 0; k < n; ++k) s += M0s[i * n + k] * T[k * P + j];
        A[i * P + j] = s;
    }
    __syncthreads();
    for (int idx = tid; idx < n * n; idx += TPBJ) {     // T = A * M0s = G
        int i = idx / n, j = idx - i * n;
        float s = 0.0f;
        for (int k = 0; k < n; ++k) s += A[i * P + k] * M0s[k * n + j];
        T[i * P + j] = s;
    }
    __syncthreads();
    for (int idx = tid; idx < n * n; idx += TPBJ) {     // A = sym(G)
        int i = idx / n, j = idx - i * n;
        A[i * P + j] = 0.5f * (T[i * P + j] + T[j * P + i]);
    }
    __syncthreads();
    jacobi_sym<n, TPBJ>(A, V);
    if (tid < n) vec[tid] = 1.0f / sqrtf(fmaxf(A[tid * P + tid], 1e-30f));
    __syncthreads();
    for (int idx = tid; idx < n * n; idx += TPBJ) {     // T = Gis
        int i = idx / n, j = idx - i * n;
        float s = 0.0f;
        for (int k = 0; k < n; ++k) s += V[i * P + k] * vec[k] * V[j * P + k];
        T[i * P + j] = s;
    }
    __syncthreads();
    for (int idx = tid; idx < n * n; idx += TPBJ) {     // A = sym(G_weight)
        int i = idx / n, j = idx - i * n;
        A[i * P + j] = 0.5f * (Gw[i * n + j] + Gw[j * n + i]);
    }
    __syncthreads();
    jacobi_sym<n, TPBJ>(A, V);
    if (tid < n) vec[tid] = sqrtf(fmaxf(A[tid * P + tid], 0.0f));
    __syncthreads();
    // A = diag(vec) V^T T
    for (int idx = tid; idx < n * n; idx += TPBJ) {
        int k = idx / n, j = idx - k * n;
        float s = 0.0f;
        for (int i = 0; i < n; ++i) s += V[i * P + k] * T[i * P + j];
        A[k * P + j] = vec[k] * s;
    }
    __syncthreads();
    // C = V A  (= Ws * Gis)
    for (int idx = tid; idx < n * n; idx += TPBJ) {
        int i = idx / n, j = idx - i * n;
        float s = 0.0f;
        for (int k = 0; k < n; ++k) s += V[i * P + k] * A[k * P + j];
        Cout[idx] = s;
    }
}

// ---------------- final linear: y = v Wl^T + bl ----------------
__global__ void __launch_bounds__(TPB) linear_kernel(const float* __restrict__ v,
                                                     const float* __restrict__ Wl,
                                                     const float* __restrict__ bl,
                                                     float* __restrict__ y) {
    __shared__ float r0[TPB], r1[TPB];
    const int b = blockIdx.x, tid = threadIdx.x;
    const float* vb = v + (size_t)b * 2500;
    float a0 = 0.0f, a1 = 0.0f;
    for (int k = tid; k < 2500; k += TPB) {
        float vv = vb[k];
        a0 += vv * Wl[k];
        a1 += vv * Wl[2500 + k];
    }
    r0[tid] = a0; r1[tid] = a1;
    __syncthreads();
    for (int s = TPB / 2; s > 0; s >>= 1) {
        if (tid < s) { r0[tid] += r0[tid + s]; r1[tid] += r1[tid + s]; }
        __syncthreads();
    }
    if (tid == 0) {
        y[b * 2 + 0] = r0[0] + bl[0];
        y[b * 2 + 1] = r1[0] + bl[1];
    }
}

extern "C" void kernel_launch(void* const* d_in, const int* in_sizes, int n_in,
                              void* d_out, int out_size) {
    (void)in_sizes; (void)n_in; (void)out_size;
    const float* x  = (const float*)d_in[0];
    const float* W1 = (const float*)d_in[1];
    const float* W2 = (const float*)d_in[2];
    const float* W3 = (const float*)d_in[3];
    const float* G1 = (const float*)d_in[4];
    const float* G2 = (const float*)d_in[5];
    const float* G3 = (const float*)d_in[6];
    const float* Wl = (const float*)d_in[7];
    const float* bl = (const float*)d_in[8];

    float* y    = (float*)d_out;
    float* feat = y + NBATCH * 2;

    float *bufA, *bufB, *mean, *M0s, *M0is, *Cm;
    double* part;
    cudaGetSymbolAddress((void**)&bufA, g_bufA);
    cudaGetSymbolAddress((void**)&bufB, g_bufB);
    cudaGetSymbolAddress((void**)&part, g_part);
    cudaGetSymbolAddress((void**)&mean, g_mean);
    cudaGetSymbolAddress((void**)&M0s,  g_M0s);
    cudaGetSymbolAddress((void**)&M0is, g_M0is);
    cudaGetSymbolAddress((void**)&Cm,   g_C);

    // ---------------- layer 1: 62 -> 58 ----------------
    congr_kernel<62, 58><<<NBATCH, TPB>>>(x, W1, bufA);
    reduce_partial_kernel<58><<<64, TPB>>>(bufA, part);
    reduce_final_kernel<58><<<1, TPB>>>(part, mean);
    stats1_kernel<58><<<1, TPBJ>>>(mean, M0s, M0is);
    congr_kernel<58, 58><<<NBATCH, TPB>>>(bufA, M0is, bufB);          // Y = M0is X M0is
    jacobi_fn_kernel<58, F_LOG><<<NBATCH, TPBJ>>>(bufB, bufB);        // logm(Y)
    reduce_partial_kernel<58><<<64, TPB>>>(bufB, part);
    reduce_final_kernel<58><<<1, TPB>>>(part, mean);                  // L
    stats2_kernel<58><<<1, TPBJ>>>(mean, M0s, G1, Cm);                // C = Ws*Gis
    congr_kernel<58, 58><<<NBATCH, TPB>>>(bufA, Cm, bufB);            // BN out
    jacobi_fn_kernel<58, F_CLAMP><<<NBATCH, TPBJ>>>(bufB, bufB);      // ReEig

    // ---------------- layer 2: 58 -> 54 ----------------
    congr_kernel<58, 54><<<NBATCH, TPB>>>(bufB, W2, bufA);
    reduce_partial_kernel<54><<<64, TPB>>>(bufA, part);
    reduce_final_kernel<54><<<1, TPB>>>(part, mean);
    stats1_kernel<54><<<1, TPBJ>>>(mean, M0s, M0is);
    congr_kernel<54, 54><<<NBATCH, TPB>>>(bufA, M0is, bufB);
    jacobi_fn_kernel<54, F_LOG><<<NBATCH, TPBJ>>>(bufB, bufB);
    reduce_partial_kernel<54><<<64, TPB>>>(bufB, part);
    reduce_final_kernel<54><<<1, TPB>>>(part, mean);
    stats2_kernel<54><<<1, TPBJ>>>(mean, M0s, G2, Cm);
    congr_kernel<54, 54><<<NBATCH, TPB>>>(bufA, Cm, bufB);
    jacobi_fn_kernel<54, F_CLAMP><<<NBATCH, TPBJ>>>(bufB, bufB);

    // ---------------- layer 3: 54 -> 50 (no ReEig; output = feat) ----------------
    congr_kernel<54, 50><<<NBATCH, TPB>>>(bufB, W3, bufA);
    reduce_partial_kernel<50><<<64, TPB>>>(bufA, part);
    reduce_final_kernel<50><<<1, TPB>>>(part, mean);
    stats1_kernel<50><<<1, TPBJ>>>(mean, M0s, M0is);
    congr_kernel<50, 50><<<NBATCH, TPB>>>(bufA, M0is, bufB);
    jacobi_fn_kernel<50, F_LOG><<<NBATCH, TPBJ>>>(bufB, bufB);
    reduce_partial_kernel<50><<<64, TPB>>>(bufB, part);
    reduce_final_kernel<50><<<1, TPB>>>(part, mean);
    stats2_kernel<50><<<1, TPBJ>>>(mean, M0s, G3, Cm);
    congr_kernel<50, 50><<<NBATCH, TPB>>>(bufA, Cm, feat);            // feat -> d_out

    // ---------------- LogEig + linear head ----------------
    jacobi_fn_kernel<50, F_LOG><<<NBATCH, TPBJ>>>(feat, bufA);        // v = logm(feat)
    linear_kernel<<<NBATCH, TPB>>>(bufA, Wl, bl, y);
}

// round 10
// speedup vs baseline: 1.0457x; 1.0457x over previous
#include <cuda_runtime.h>

#define NBATCH 8192
#define TPB   256   // congruence / reduction kernels
#define TPBJ  128   // batched Jacobi kernels
#define TPBS  256   // single-matrix stats kernels (latency-bound -> more threads)

typedef unsigned long long ull;

// ---------------- packed f32x2 helpers (sm_103a FFMA2 path) ----------------
__device__ __forceinline__ ull f2mul(ull a, ull b) {
    ull r; asm("mul.rn.f32x2 %0, %1, %2;" : "=l"(r) : "l"(a), "l"(b)); return r;
}
__device__ __forceinline__ ull f2fma(ull a, ull b, ull c) {
    ull r; asm("fma.rn.f32x2 %0, %1, %2, %3;" : "=l"(r) : "l"(a), "l"(b), "l"(c)); return r;
}
__device__ __forceinline__ ull f2dup(float x) {
    unsigned int u = __float_as_uint(x);
    ull r; asm("mov.b64 %0, {%1, %1};" : "=l"(r) : "r"(u)); return r;
}

// ---------------- device scratch (static, no runtime allocation) ----------------
__device__ float  g_bufA[(size_t)NBATCH * 58 * 58];
__device__ float  g_bufB[(size_t)NBATCH * 58 * 58];
__device__ double g_part[64 * 58 * 58];
__device__ float  g_mean[58 * 58];
__device__ float  g_M0s [58 * 58];
__device__ float  g_M0is[58 * 58];
__device__ float  g_C   [58 * 58];

// ---------------- block reduction helper: returns total in red_[0] ----------------
template<int BS>
__device__ __forceinline__ void block_reduce(float v, float* red_) {
    const int tid  = threadIdx.x;
    const int lane = tid & 31;
    const int wrp  = tid >> 5;
    #pragma unroll
    for (int o = 16; o > 0; o >>= 1) v += __shfl_down_sync(0xffffffffu, v, o);
    if (lane == 0) red_[wrp] = v;
    __syncthreads();
    if (wrp == 0) {
        float t = (lane < BS / 32) ? red_[lane] : 0.0f;
        #pragma unroll
        for (int o = 16; o > 0; o >>= 1) t += __shfl_down_sync(0xffffffffu, t, o);
        if (lane == 0) red_[0] = t;
    }
    __syncthreads();
}

// ---------------- round-robin pairing (circle method, n even) ----------------
__device__ __forceinline__ void pair_of(int r, int k, int n, int& p, int& q) {
    int m = n - 1;
    if (k == 0) { p = n - 1; q = r; }
    else {
        p = r + k; if (p >= m) p -= m;
        q = r - k; if (q < 0)  q += m;
    }
}

// ---------------- block-cooperative cyclic Jacobi, pitch = n (even, f32x2-aligned) ----
// On exit: diag(A) = eigenvalues; VT rows = eigenvectors (A0 = VT^T diag VT).
// Row phases (A rows, VT rows) use LDS.64 + packed f32x2 math; the A column
// phase is scalar (2-way bank conflict for gcd(n,32)=2 — throughput only).
template<int n, int BS>
__device__ void jacobi_sym(float* A, float* VT) {
    static_assert(n % 2 == 0, "n even");
    constexpr int NPAIR = n / 2;
    constexpr int NH = n / 2;            // float2 columns per row
    static_assert(NH <= 32, "NH fits 32-layout");
    const int tid = threadIdx.x;
    __shared__ float cs_[NPAIR], ss_[NPAIR];
    __shared__ ull   cc2_[NPAIR], ss2_[NPAIR], nss2_[NPAIR];
    __shared__ int   ppr_[NPAIR], qqr_[NPAIR];   // p*n, q*n
    __shared__ int   ppc_[NPAIR], qqc_[NPAIR];   // p,   q
    __shared__ float red_[32];
    __shared__ float s_thr;

    for (int idx = tid; idx < n * n; idx += BS) {
        int i = idx / n, j = idx - i * n;
        VT[idx] = (i == j) ? 1.0f : 0.0f;
    }
    float facc = 0.0f;
    for (int idx = tid; idx < n * n; idx += BS) {
        float v = A[idx];
        facc += v * v;
    }
    __syncthreads();
    block_reduce<BS>(facc, red_);
    // fp32 Jacobi off-diagonal floor: off^2/fro^2 ~ n*eps^2. Stop just above it.
    if (tid == 0) s_thr = red_[0] * 1e-12f + 1e-37f;
    __syncthreads();

    for (int sweep = 0; sweep < 14; ++sweep) {
        for (int r = 0; r < n - 1; ++r) {
            if (tid < NPAIR) {
                int p, q; pair_of(r, tid, n, p, q);
                ppr_[tid] = p * n;  qqr_[tid] = q * n;
                ppc_[tid] = p;      qqc_[tid] = q;
                float app = A[p * n + p], aqq = A[q * n + q], apq = A[p * n + q];
                float c = 1.0f, s = 0.0f;
                if (fabsf(apq) > 1e-38f) {
                    float tau = (aqq - app) / (2.0f * apq);
                    float t = 1.0f / (fabsf(tau) + sqrtf(1.0f + tau * tau));
                    if (tau < 0.0f) t = -t;
                    c = 1.0f / sqrtf(1.0f + t * t);
                    s = t * c;
                }
                cs_[tid] = c; ss_[tid] = s;
                cc2_[tid] = f2dup(c); ss2_[tid] = f2dup(s); nss2_[tid] = f2dup(-s);
            }
            __syncthreads();
            // row phase: A <- J^T A  (float2; k = w>>5, j2 = w&31)
            for (int w = tid; w < NPAIR * 32; w += BS) {
                int k = w >> 5, j2 = w & 31;
                if (j2 < NH) {
                    int pP = ppr_[k] + 2 * j2, qP = qqr_[k] + 2 * j2;
                    ull ap = *reinterpret_cast<ull*>(&A[pP]);
                    ull aq = *reinterpret_cast<ull*>(&A[qP]);
                    ull cc = cc2_[k];
                    *reinterpret_cast<ull*>(&A[pP]) = f2fma(nss2_[k], aq, f2mul(cc, ap));
                    *reinterpret_cast<ull*>(&A[qP]) = f2fma(ss2_[k],  ap, f2mul(cc, aq));
                }
            }
            __syncthreads();
            // col phase on A (scalar), then row phase on VT (float2) — disjoint arrays
            for (int w = tid; w < NPAIR * 64; w += BS) {
                int k = w >> 6, j = w & 63;
                if (j < n) {
                    int jP = j * n;
                    int p = ppc_[k], q = qqc_[k];
                    float c = cs_[k], s = ss_[k];
                    float ap = A[jP + p], aq = A[jP + q];
                    A[jP + p] = c * ap - s * aq;
                    A[jP + q] = s * ap + c * aq;
                }
            }
            for (int w = tid; w < NPAIR * 32; w += BS) {
                int k = w >> 5, j2 = w & 31;
                if (j2 < NH) {
                    int pP = ppr_[k] + 2 * j2, qP = qqr_[k] + 2 * j2;
                    ull vp = *reinterpret_cast<ull*>(&VT[pP]);
                    ull vq = *reinterpret_cast<ull*>(&VT[qP]);
                    ull cc = cc2_[k];
                    *reinterpret_cast<ull*>(&VT[pP]) = f2fma(nss2_[k], vq, f2mul(cc, vp));
                    *reinterpret_cast<ull*>(&VT[qP]) = f2fma(ss2_[k],  vp, f2mul(cc, vq));
                }
            }
            __syncthreads();
        }
        if (sweep < 3) continue;   // never converges this early for n>=50
        float oacc = 0.0f;
        for (int w = tid; w < n * 64; w += BS) {
            int i = w >> 6, j = w & 63;
            if (j < n && i != j) { float v = A[i * n + j]; oacc += v * v; }
        }
        block_reduce<BS>(oacc, red_);
        if (red_[0] < s_thr) break;
        __syncthreads();
    }
    __syncthreads();
}

// ---------------- batched eigen-function: out = VT^T f(Lam) VT ----------------
#define F_LOG   0
#define F_CLAMP 1

template<int n, int FN>
__global__ void __launch_bounds__(TPBJ) jacobi_fn_kernel(const float* __restrict__ in,
                                                         float* __restrict__ out) {
    __shared__ __align__(16) float A[n * n];
    __shared__ __align__(16) float VT[n * n];
    __shared__ float fv[n];
    const float* g = in  + (size_t)blockIdx.x * n * n;
    float*       o = out + (size_t)blockIdx.x * n * n;
    const int tid = threadIdx.x;
    for (int idx = tid; idx < n * n; idx += TPBJ) {
        int i = idx / n, j = idx - i * n;
        A[idx] = 0.5f * (g[idx] + g[j * n + i]);
    }
    __syncthreads();
    jacobi_sym<n, TPBJ>(A, VT);
    if (tid < n) {
        float l = A[tid * n + tid];
        fv[tid] = (FN == F_LOG) ? logf(fmaxf(l, 1e-30f)) : fmaxf(l, 1e-4f);
    }
    __syncthreads();
    // A <- diag(fv) * VT   (row-scaled)
    for (int idx = tid; idx < n * n; idx += TPBJ) {
        int k = idx / n;
        A[idx] = fv[k] * VT[idx];
    }
    __syncthreads();
    // out[i][j..j+1] = sum_k VT[k][i] * A[k][j..j+1]   (float2)
    for (int w = tid; w < n * 32; w += TPBJ) {
        int i = w >> 5, j2 = w & 31;
        if (j2 < n / 2) {
            ull acc = 0ull;   // (0.0f, 0.0f)
            #pragma unroll 2
            for (int k = 0; k < n; ++k) {
                ull vv = f2dup(VT[k * n + i]);
                acc = f2fma(vv, *reinterpret_cast<ull*>(&A[k * n + 2 * j2]), acc);
            }
            *reinterpret_cast<ull*>(&o[(size_t)i * n + 2 * j2]) = acc;
        }
    }
}

// ---------------- batched congruence: out = P X P^T  (P: NO x NI) ----------------
template<int NI, int NO>
__global__ void __launch_bounds__(TPB) congr_kernel(const float* __restrict__ Xin,
                                                    const float* __restrict__ Pm,
                                                    float* __restrict__ out) {
    constexpr int PI = NI + 1;
    __shared__ float Xs[NI * PI];
    __shared__ float Ps[NO * PI];
    __shared__ float Ts[NO * PI];
    const float* g = Xin + (size_t)blockIdx.x * NI * NI;
    float*       o = out + (size_t)blockIdx.x * NO * NO;
    const int tid = threadIdx.x;
    for (int idx = tid; idx < NI * NI; idx += TPB) {
        int i = idx / NI, j = idx - i * NI;
        Xs[i * PI + j] = g[idx];
    }
    for (int idx = tid; idx < NO * NI; idx += TPB) {
        int a = idx / NI, i = idx - a * NI;
        Ps[a * PI + i] = Pm[idx];
    }
    __syncthreads();
    for (int idx = tid; idx < NO * NI; idx += TPB) {
        int a = idx / NI, j = idx - a * NI;
        float s = 0.0f;
        #pragma unroll 2
        for (int i = 0; i < NI; ++i) s += Ps[a * PI + i] * Xs[i * PI + j];
        Ts[a * PI + j] = s;
    }
    __syncthreads();
    for (int idx = tid; idx < NO * NO; idx += TPB) {
        int a = idx / NO, b = idx - a * NO;
        float s = 0.0f;
        #pragma unroll 2
        for (int j = 0; j < NI; ++j) s += Ts[a * PI + j] * Ps[b * PI + j];
        o[idx] = s;
    }
}

// ---------------- deterministic two-stage batch-mean reduction ----------------
template<int n>
__global__ void __launch_bounds__(TPB) reduce_partial_kernel(const float* __restrict__ buf,
                                                             double* __restrict__ part) {
    const int b = blockIdx.x;          // 64 blocks
    const int tid = threadIdx.x;
    constexpr int CH = NBATCH / 64;    // 128 matrices per block
    for (int e = tid; e < n * n; e += TPB) {
        double acc = 0.0;
        for (int m = 0; m < CH; ++m)
            acc += (double)buf[((size_t)(b * CH + m)) * (n * n) + e];
        part[(size_t)b * (n * n) + e] = acc;
    }
}

template<int n>
__global__ void __launch_bounds__(TPB) reduce_final_kernel(const double* __restrict__ part,
                                                           float* __restrict__ mean) {
    const int tid = threadIdx.x;
    for (int e = tid; e < n * n; e += TPB) {
        double acc = 0.0;
        for (int b = 0; b < 64; ++b) acc += part[(size_t)b * (n * n) + e];
        mean[e] = (float)(acc * (1.0 / (double)NBATCH));
    }
}

// ---------------- single-matrix stats: M0 -> sqrtm, isqrtm ----------------
template<int n>
__global__ void __launch_bounds__(TPBS) stats1_kernel(const float* __restrict__ mean,
                                                      float* __restrict__ M0s,
                                                      float* __restrict__ M0is) {
    __shared__ __align__(16) float A[n * n];
    __shared__ __align__(16) float VT[n * n];
    __shared__ float sq[n], isq[n];
    const int tid = threadIdx.x;
    for (int idx = tid; idx < n * n; idx += TPBS) {
        int i = idx / n, j = idx - i * n;
        A[idx] = 0.5f * (mean[idx] + mean[j * n + i]);
    }
    __syncthreads();
    jacobi_sym<n, TPBS>(A, VT);
    if (tid < n) {
        float l = fmaxf(A[tid * n + tid], 1e-30f);
        float s = sqrtf(l);
        sq[tid] = s;
        isq[tid] = 1.0f / s;
    }
    __syncthreads();
    for (int idx = tid; idx < n * n; idx += TPBS) {
        int i = idx / n, j = idx - i * n;
        float s1 = 0.0f, s2 = 0.0f;
        for (int k = 0; k < n; ++k) {
            float vv = VT[k * n + i] * VT[k * n + j];
            s1 += vv * sq[k];
            s2 += vv * isq[k];
        }
        M0s[idx]  = s1;
        M0is[idx] = s2;
    }
}

// ---------------- single-matrix stats2: L, M0s, G_weight -> C = sqrtm(Gw) * isqrtm(G) ----
// G = sym(M0s expm(L) M0s)
template<int n>
__global__ void __launch_bounds__(TPBS) stats2_kernel(const float* __restrict__ Lmean,
                                                      const float* __restrict__ M0s,
                                                      const float* __restrict__ Gw,
                                                      float* __restrict__ Cout) {
    __shared__ __align__(16) float A[n * n];
    __shared__ __align__(16) float VT[n * n];
    __shared__ __align__(16) float T[n * n];
    __shared__ float vec[n];
    const int tid = threadIdx.x;
    // E = expm(L)
    for (int idx = tid; idx < n * n; idx += TPBS) {
        int i = idx / n, j = idx - i * n;
        A[idx] = 0.5f * (Lmean[idx] + Lmean[j * n + i]);
    }
    __syncthreads();
    jacobi_sym<n, TPBS>(A, VT);
    if (tid < n) vec[tid] = expf(A[tid * n + tid]);
    __syncthreads();
    for (int idx = tid; idx < n * n; idx += TPBS) {     // T = E
        int i = idx / n, j = idx - i * n;
        float s = 0.0f;
        for (int k = 0; k < n; ++k) s += VT[k * n + i] * vec[k] * VT[k * n + j];
        T[idx] = s;
    }
    __syncthreads();
    for (int idx = tid; idx < n * n; idx += TPBS) {     // A = M0s * E
        int i = idx / n, j = idx - i * n;
        float s = 0.0f;
        for (int k = 0; k < n; ++k) s += M0s[i * n + k] * T[k * n + j];
        A[idx] = s;
    }
    __syncthreads();
    for (int idx = tid; idx < n * n; idx += TPBS) {     // T = A * M0s = G
        int i = idx / n, j = idx - i * n;
        float s = 0.0f;
        for (int k = 0; k < n; ++k) s += A[i * n + k] * M0s[k * n + j];
        T[idx] = s;
    }
    __syncthreads();
    for (int idx = tid; idx < n * n; idx += TPBS) {     // A = sym(G)
        int i = idx / n, j = idx - i * n;
        A[idx] = 0.5f * (T[idx] + T[j * n + i]);
    }
    __syncthreads();
    jacobi_sym<n, TPBS>(A, VT);
    if (tid < n) vec[tid] = 1.0f / sqrtf(fmaxf(A[tid * n + tid], 1e-30f));
    __syncthreads();
    for (int idx = tid; idx < n * n; idx += TPBS) {     // T = Gis
        int i = idx / n, j = idx - i * n;
        float s = 0.0f;
        for (int k = 0; k < n; ++k) s += VT[k * n + i] * vec[k] * VT[k * n + j];
        T[idx] = s;
    }
    __syncthreads();
    for (int idx = tid; idx < n * n; idx += TPBS) {     // A = sym(G_weight)
        int i = idx / n, j = idx - i * n;
        A[idx] = 0.5f * (Gw[idx] + Gw[j * n + i]);
    }
    __syncthreads();
    jacobi_sym<n, TPBS>(A, VT);
    if (tid < n) vec[tid] = sqrtf(fmaxf(A[tid * n + tid], 0.0f));
    __syncthreads();
    // A = diag(vec) V^T T :  A[k][j] = vec[k] * sum_i VT[k][i] T[i][j]
    for (int idx = tid; idx < n * n; idx += TPBS) {
        int k = idx / n, j = idx - k * n;
        float s = 0.0f;
        for (int i = 0; i < n; ++i) s += VT[k * n + i] * T[i * n + j];
        A[idx] = vec[k] * s;
    }
    __syncthreads();
    // C = V A :  C[i][j] = sum_k VT[k][i] A[k][j]
    for (int idx = tid; idx < n * n; idx += TPBS) {
        int i = idx / n, j = idx - i * n;
        float s = 0.0f;
        for (int k = 0; k < n; ++k) s += VT[k * n + i] * A[k * n + j];
        Cout[idx] = s;
    }
}

// ---------------- final linear: y = v Wl^T + bl ----------------
__global__ void __launch_bounds__(TPB) linear_kernel(const float* __restrict__ v,
                                                     const float* __restrict__ Wl,
                                                     const float* __restrict__ bl,
                                                     float* __restrict__ y) {
    __shared__ float r0[TPB], r1[TPB];
    const int b = blockIdx.x, tid = threadIdx.x;
    const float* vb = v + (size_t)b * 2500;
    float a0 = 0.0f, a1 = 0.0f;
    for (int k = tid; k < 2500; k += TPB) {
        float vv = vb[k];
        a0 += vv * Wl[k];
        a1 += vv * Wl[2500 + k];
    }
    r0[tid] = a0; r1[tid] = a1;
    __syncthreads();
    for (int s = TPB / 2; s > 0; s >>= 1) {
        if (tid < s) { r0[tid] += r0[tid + s]; r1[tid] += r1[tid + s]; }
        __syncthreads();
    }
    if (tid == 0) {
        y[b * 2 + 0] = r0[0] + bl[0];
        y[b * 2 + 1] = r1[0] + bl[1];
    }
}

extern "C" void kernel_launch(void* const* d_in, const int* in_sizes, int n_in,
                              void* d_out, int out_size) {
    (void)in_sizes; (void)n_in; (void)out_size;
    const float* x  = (const float*)d_in[0];
    const float* W1 = (const float*)d_in[1];
    const float* W2 = (const float*)d_in[2];
    const float* W3 = (const float*)d_in[3];
    const float* G1 = (const float*)d_in[4];
    const float* G2 = (const float*)d_in[5];
    const float* G3 = (const float*)d_in[6];
    const float* Wl = (const float*)d_in[7];
    const float* bl = (const float*)d_in[8];

    float* y    = (float*)d_out;
    float* feat = y + NBATCH * 2;

    float *bufA, *bufB, *mean, *M0s, *M0is, *Cm;
    double* part;
    cudaGetSymbolAddress((void**)&bufA, g_bufA);
    cudaGetSymbolAddress((void**)&bufB, g_bufB);
    cudaGetSymbolAddress((void**)&part, g_part);
    cudaGetSymbolAddress((void**)&mean, g_mean);
    cudaGetSymbolAddress((void**)&M0s,  g_M0s);
    cudaGetSymbolAddress((void**)&M0is, g_M0is);
    cudaGetSymbolAddress((void**)&Cm,   g_C);

    // ---------------- layer 1: 62 -> 58 ----------------
    congr_kernel<62, 58><<<NBATCH, TPB>>>(x, W1, bufA);
    reduce_partial_kernel<58><<<64, TPB>>>(bufA, part);
    reduce_final_kernel<58><<<1, TPB>>>(part, mean);
    stats1_kernel<58><<<1, TPBS>>>(mean, M0s, M0is);
    congr_kernel<58, 58><<<NBATCH, TPB>>>(bufA, M0is, bufB);          // Y = M0is X M0is
    jacobi_fn_kernel<58, F_LOG><<<NBATCH, TPBJ>>>(bufB, bufB);        // logm(Y)
    reduce_partial_kernel<58><<<64, TPB>>>(bufB, part);
    reduce_final_kernel<58><<<1, TPB>>>(part, mean);                  // L
    stats2_kernel<58><<<1, TPBS>>>(mean, M0s, G1, Cm);                // C = Ws*Gis
    congr_kernel<58, 58><<<NBATCH, TPB>>>(bufA, Cm, bufB);            // BN out
    jacobi_fn_kernel<58, F_CLAMP><<<NBATCH, TPBJ>>>(bufB, bufB);      // ReEig

    // ---------------- layer 2: 58 -> 54 ----------------
    congr_kernel<58, 54><<<NBATCH, TPB>>>(bufB, W2, bufA);
    reduce_partial_kernel<54><<<64, TPB>>>(bufA, part);
    reduce_final_kernel<54><<<1, TPB>>>(part, mean);
    stats1_kernel<54><<<1, TPBS>>>(mean, M0s, M0is);
    congr_kernel<54, 54><<<NBATCH, TPB>>>(bufA, M0is, bufB);
    jacobi_fn_kernel<54, F_LOG><<<NBATCH, TPBJ>>>(bufB, bufB);
    reduce_partial_kernel<54><<<64, TPB>>>(bufB, part);
    reduce_final_kernel<54><<<1, TPB>>>(part, mean);
    stats2_kernel<54><<<1, TPBS>>>(mean, M0s, G2, Cm);
    congr_kernel<54, 54><<<NBATCH, TPB>>>(bufA, Cm, bufB);
    jacobi_fn_kernel<54, F_CLAMP><<<NBATCH, TPBJ>>>(bufB, bufB);

    // ---------------- layer 3: 54 -> 50 (no ReEig; output = feat) ----------------
    congr_kernel<54, 50><<<NBATCH, TPB>>>(bufB, W3, bufA);
    reduce_partial_kernel<50><<<64, TPB>>>(bufA, part);
    reduce_final_kernel<50><<<1, TPB>>>(part, mean);
    stats1_kernel<50><<<1, TPBS>>>(mean, M0s, M0is);
    congr_kernel<50, 50><<<NBATCH, TPB>>>(bufA, M0is, bufB);
    jacobi_fn_kernel<50, F_LOG><<<NBATCH, TPBJ>>>(bufB, bufB);
    reduce_partial_kernel<50><<<64, TPB>>>(bufB, part);
    reduce_final_kernel<50><<<1, TPB>>>(part, mean);
    stats2_kernel<50><<<1, TPBS>>>(mean, M0s, G3, Cm);
    congr_kernel<50, 50><<<NBATCH, TPB>>>(bufA, Cm, feat);            // feat -> d_out

    // ---------------- LogEig + linear head ----------------
    jacobi_fn_kernel<50, F_LOG><<<NBATCH, TPBJ>>>(feat, bufA);        // v = logm(feat)
    linear_kernel<<<NBATCH, TPB>>>(bufA, Wl, bl, y);
}